// round 1
// baseline (speedup 1.0000x reference)
#include <cuda_runtime.h>
#include <cstdint>

#define Bn 64
#define Cn 64
#define On 64
#define Hn 32
#define Wn 32
#define Ln 1024
#define KKn 576
#define HP 34
#define WP 34

// padded, transposed x: [c][hp][wp][b], b innermost for coalesced unfold gathers
__device__ float g_xTp[Cn * HP * WP * Bn];

// ---------------------------------------------------------------------------
// Kernel 1: zero the padded border of g_xTp
// ---------------------------------------------------------------------------
__global__ void border_kernel() {
    int idx = blockIdx.x * 256 + threadIdx.x;       // 64 c * 132 border cells * 64 b
    if (idx >= Cn * 132 * Bn) return;
    int b = idx & 63;
    int r = idx >> 6;
    int c = r / 132;
    int cell = r % 132;
    int hp, wp;
    if (cell < 34)       { hp = 0;  wp = cell; }
    else if (cell < 68)  { hp = 33; wp = cell - 34; }
    else if (cell < 100) { hp = cell - 68 + 1;  wp = 0; }
    else                 { hp = cell - 100 + 1; wp = 33; }
    g_xTp[((c * HP + hp) * WP + wp) * Bn + b] = 0.0f;
}

// ---------------------------------------------------------------------------
// Kernel 2: transpose x (B,C,H,W) -> xTp[c][h+1][w+1][b] via smem tile
// ---------------------------------------------------------------------------
__global__ void transpose_kernel(const float* __restrict__ x) {
    __shared__ float t[32][65];
    int c = blockIdx.x & 63;
    int h = blockIdx.x >> 6;
    int tid = threadIdx.x;

    int w  = tid & 31;
    int b0 = tid >> 5;                     // 0..7
#pragma unroll
    for (int p = 0; p < 8; p++) {
        int b = b0 * 8 + p;
        t[w][b] = x[((b * Cn + c) * Hn + h) * Wn + w];  // 128B coalesced reads
    }
    __syncthreads();
    int b  = tid & 63;
    int wq = tid >> 6;                     // 0..3
#pragma unroll
    for (int p = 0; p < 8; p++) {
        int ww = wq * 8 + p;
        g_xTp[((c * HP + (h + 1)) * WP + (ww + 1)) * Bn + b] = t[ww][b];  // 256B coalesced writes
    }
}

// ---------------------------------------------------------------------------
// Kernel 3: main locally-connected GEMM
//   grid = 128 CTAs (8 pixels each), 512 threads
//   thread tid -> (b_t = tid&7, o_t = (tid>>3)&7, l = tid>>6)
//   per-thread 8o x 8b outer product at one pixel, fp32x2-packed over o
// ---------------------------------------------------------------------------
__device__ __forceinline__ void cpa16(float* dst, const float* src) {
    unsigned d = (unsigned)__cvta_generic_to_shared(dst);
    asm volatile("cp.async.cg.shared.global [%0], [%1], 16;" :: "r"(d), "l"(src));
}
__device__ __forceinline__ unsigned long long pk(float v) {
    unsigned long long r;
    asm("mov.b64 %0, {%1, %1};" : "=l"(r) : "f"(v));
    return r;
}
#define FFMA2(a, wv, uv) asm("fma.rn.f32x2 %0, %1, %2, %0;" : "+l"(a) : "l"(wv), "l"(uv))

__global__ __launch_bounds__(512, 1)
void lc_kernel(const float* __restrict__ weight, const float* __restrict__ bias,
               float* __restrict__ out) {
    extern __shared__ float smem[];
    float* w_s = smem;            // [2][8k][8l][64o]  (16KB per buf)
    float* u_s = smem + 8192;     // [2][8k][8l][64b]

    const int tid = threadIdx.x;
    const int bt  = tid & 7;
    const int ot  = (tid >> 3) & 7;
    const int lv  = tid >> 6;
    const int l0  = blockIdx.x << 3;
    const int h   = l0 >> 5;         // row (constant for the whole CTA)
    const int w0  = l0 & 31;

    // u cp.async mapping: thread covers 2 float4s (k2 and k2+4), fixed (l,b4)
    const int ub4  = tid & 15;
    const int ul   = (tid >> 4) & 7;
    const int uk2a = tid >> 7;       // 0..3

    // w LDG/STS mapping: thread covers (o, k2), 8 l-values (32B contiguous in gmem)
    const int wo  = tid & 63;
    const int wk2 = tid >> 6;        // 0..7

    unsigned long long acc[4][8];
#pragma unroll
    for (int i = 0; i < 4; i++)
#pragma unroll
        for (int j = 0; j < 8; j++) acc[i][j] = 0ULL;

    // ---- helpers as lambdas ----
    auto issue_u = [&](int ch, int buf) {
#pragma unroll
        for (int t = 0; t < 2; t++) {
            int k2 = uk2a + 4 * t;
            int k  = ch * 8 + k2;
            int c   = (k * 7282) >> 16;        // k/9, exact for k<576
            int rem = k - 9 * c;
            int i   = (rem * 11) >> 5;         // rem/3
            int j   = rem - 3 * i;
            const float* src = g_xTp + (((c * HP) + h + i) * WP + (w0 + ul + j)) * Bn + (ub4 << 2);
            cpa16(u_s + buf * 4096 + (k2 * 8 + ul) * 64 + (ub4 << 2), src);
        }
        asm volatile("cp.async.commit_group;");
    };
    auto load_w = [&](int ch, float4& r0, float4& r1) {
        const float* src = weight + ((size_t)(wo * KKn + ch * 8 + wk2)) * Ln + l0;
        r0 = *(const float4*)(src);
        r1 = *(const float4*)(src + 4);
    };
    auto sts_w = [&](int buf, const float4& r0, const float4& r1) {
        float* wd = w_s + buf * 4096 + wk2 * 512 + wo;   // [k2][l][o], store l=0..7
        wd[0 * 64] = r0.x; wd[1 * 64] = r0.y; wd[2 * 64] = r0.z; wd[3 * 64] = r0.w;
        wd[4 * 64] = r1.x; wd[5 * 64] = r1.y; wd[6 * 64] = r1.z; wd[7 * 64] = r1.w;
    };

    // ---- pipeline prologue ----
    issue_u(0, 0);
    float4 wr0, wr1, wn0, wn1;
    load_w(0, wr0, wr1);

    const float* wbase0 = w_s + lv * 64 + ot * 8;
    const float* ubase0 = u_s + lv * 64 + bt * 8;

    for (int ch = 0; ch < 72; ch++) {
        int buf = ch & 1;
        sts_w(buf, wr0, wr1);
        if (ch + 1 < 72) {
            issue_u(ch + 1, buf ^ 1);
            load_w(ch + 1, wn0, wn1);
            asm volatile("cp.async.wait_group 1;");
        } else {
            asm volatile("cp.async.wait_group 0;");
        }
        __syncthreads();

        const float* wb = wbase0 + buf * 4096;
        const float* ub = ubase0 + buf * 4096;
#pragma unroll
        for (int kk = 0; kk < 8; kk++) {
            ulonglong2 wa = *(const ulonglong2*)(wb + kk * 512);
            ulonglong2 wc = *(const ulonglong2*)(wb + kk * 512 + 4);
            float4 ua = *(const float4*)(ub + kk * 512);
            float4 uc = *(const float4*)(ub + kk * 512 + 4);
            unsigned long long wv[4] = { wa.x, wa.y, wc.x, wc.y };
            unsigned long long u2[8] = { pk(ua.x), pk(ua.y), pk(ua.z), pk(ua.w),
                                         pk(uc.x), pk(uc.y), pk(uc.z), pk(uc.w) };
#pragma unroll
            for (int op = 0; op < 4; op++)
#pragma unroll
                for (int j = 0; j < 8; j++)
                    FFMA2(acc[op][j], wv[op], u2[j]);
        }
        __syncthreads();
        wr0 = wn0; wr1 = wn1;
    }

    // ---- epilogue: smem transpose for 32B-per-(b,o) coalesced output writes ----
    float* s_ep = smem;   // [64 b][68 pad] : s_ep[b*68 + o_t*8 + l]
    const int wb_ = tid & 63;       // writer b
    const int wot = tid >> 6;       // writer o_t

#pragma unroll
    for (int oi = 0; oi < 8; oi++) {
        int o_mine = ot * 8 + oi;
        float bv = bias[o_mine * Ln + l0 + lv];
#pragma unroll
        for (int j = 0; j < 8; j++) {
            float2 v2 = *reinterpret_cast<float2*>(&acc[oi >> 1][j]);
            float v = (oi & 1) ? v2.y : v2.x;
            s_ep[(bt * 8 + j) * 68 + ot * 8 + lv] = v + bv;
        }
        __syncthreads();
        // each thread writes one (b, o) pair's 8 pixels (32B contiguous)
        const float* sp = s_ep + wb_ * 68 + wot * 8;
        float4 v0 = *(const float4*)(sp);
        float4 v1 = *(const float4*)(sp + 4);
        int o_w = wot * 8 + oi;
        float* dst = out + ((size_t)(wb_ * On + o_w)) * Ln + l0;
        *(float4*)(dst)     = v0;
        *(float4*)(dst + 4) = v1;
        __syncthreads();
    }
}

// ---------------------------------------------------------------------------
extern "C" void kernel_launch(void* const* d_in, const int* in_sizes, int n_in,
                              void* d_out, int out_size) {
    const float* x      = (const float*)d_in[0];
    const float* weight = (const float*)d_in[1];
    const float* bias   = (const float*)d_in[2];
    float* out = (float*)d_out;

    cudaFuncSetAttribute(lc_kernel, cudaFuncAttributeMaxDynamicSharedMemorySize, 65536);

    border_kernel<<<2112, 256>>>();
    transpose_kernel<<<Cn * Hn, 256>>>(x);
    lc_kernel<<<Ln / 8, 512, 65536>>>(weight, bias, out);
}

// round 2
// speedup vs baseline: 1.0572x; 1.0572x over previous
#include <cuda_runtime.h>
#include <cstdint>

#define Bn 64
#define Cn 64
#define On 64
#define Hn 32
#define Wn 32
#define Ln 1024
#define KKn 576
#define HP 34
#define WP 34

// padded, transposed x: [c][hp][wp][b], b innermost for coalesced unfold gathers
__device__ float g_xTp[Cn * HP * WP * Bn];

// ---------------------------------------------------------------------------
// Kernel 1: zero the padded border of g_xTp
// ---------------------------------------------------------------------------
__global__ void border_kernel() {
    int idx = blockIdx.x * 256 + threadIdx.x;       // 64 c * 132 border cells * 64 b
    if (idx >= Cn * 132 * Bn) return;
    int b = idx & 63;
    int r = idx >> 6;
    int c = r / 132;
    int cell = r % 132;
    int hp, wp;
    if (cell < 34)       { hp = 0;  wp = cell; }
    else if (cell < 68)  { hp = 33; wp = cell - 34; }
    else if (cell < 100) { hp = cell - 68 + 1;  wp = 0; }
    else                 { hp = cell - 100 + 1; wp = 33; }
    g_xTp[((c * HP + hp) * WP + wp) * Bn + b] = 0.0f;
}

// ---------------------------------------------------------------------------
// Kernel 2: transpose x (B,C,H,W) -> xTp[c][h+1][w+1][b] via smem tile
// ---------------------------------------------------------------------------
__global__ void transpose_kernel(const float* __restrict__ x) {
    __shared__ float t[32][65];
    int c = blockIdx.x & 63;
    int h = blockIdx.x >> 6;
    int tid = threadIdx.x;

    int w  = tid & 31;
    int b0 = tid >> 5;                     // 0..7
#pragma unroll
    for (int p = 0; p < 8; p++) {
        int b = b0 * 8 + p;
        t[w][b] = x[((b * Cn + c) * Hn + h) * Wn + w];  // 128B coalesced reads
    }
    __syncthreads();
    int b  = tid & 63;
    int wq = tid >> 6;                     // 0..3
#pragma unroll
    for (int p = 0; p < 8; p++) {
        int ww = wq * 8 + p;
        g_xTp[((c * HP + (h + 1)) * WP + (ww + 1)) * Bn + b] = t[ww][b];  // 256B coalesced writes
    }
}

// ---------------------------------------------------------------------------
// Kernel 3: main locally-connected GEMM
//   grid = 128 CTAs (8 pixels each), 512 threads
//   thread tid -> (b_t = tid&7, o_t = (tid>>3)&7, l = tid>>6)
//   per-thread 8o x 8b outer product at one pixel, fp32x2-packed over o
// ---------------------------------------------------------------------------
__device__ __forceinline__ void cpa16(float* dst, const float* src) {
    unsigned d = (unsigned)__cvta_generic_to_shared(dst);
    asm volatile("cp.async.cg.shared.global [%0], [%1], 16;" :: "r"(d), "l"(src));
}
__device__ __forceinline__ unsigned long long pk(float v) {
    unsigned long long r;
    asm("mov.b64 %0, {%1, %1};" : "=l"(r) : "f"(v));
    return r;
}
#define FFMA2(a, wv, uv) asm("fma.rn.f32x2 %0, %1, %2, %0;" : "+l"(a) : "l"(wv), "l"(uv))

__global__ __launch_bounds__(512, 1)
void lc_kernel(const float* __restrict__ weight, const float* __restrict__ bias,
               float* __restrict__ out) {
    extern __shared__ float smem[];
    float* w_s = smem;            // [2][8k][8l][64o]  (16KB per buf)
    float* u_s = smem + 8192;     // [2][8k][8l][64b]

    const int tid = threadIdx.x;
    const int bt  = tid & 7;
    const int ot  = (tid >> 3) & 7;
    const int lv  = tid >> 6;
    const int l0  = blockIdx.x << 3;
    const int h   = l0 >> 5;         // row (constant for the whole CTA)
    const int w0  = l0 & 31;

    // u cp.async mapping: thread covers 2 float4s (k2 and k2+4), fixed (l,b4)
    const int ub4  = tid & 15;
    const int ul   = (tid >> 4) & 7;
    const int uk2a = tid >> 7;       // 0..3

    // w LDG/STS mapping: thread covers (o, k2), 8 l-values (32B contiguous in gmem)
    const int wo  = tid & 63;
    const int wk2 = tid >> 6;        // 0..7

    unsigned long long acc[4][8];
#pragma unroll
    for (int i = 0; i < 4; i++)
#pragma unroll
        for (int j = 0; j < 8; j++) acc[i][j] = 0ULL;

    // ---- helpers as lambdas ----
    auto issue_u = [&](int ch, int buf) {
#pragma unroll
        for (int t = 0; t < 2; t++) {
            int k2 = uk2a + 4 * t;
            int k  = ch * 8 + k2;
            int c   = (k * 7282) >> 16;        // k/9, exact for k<576
            int rem = k - 9 * c;
            int i   = (rem * 11) >> 5;         // rem/3
            int j   = rem - 3 * i;
            const float* src = g_xTp + (((c * HP) + h + i) * WP + (w0 + ul + j)) * Bn + (ub4 << 2);
            cpa16(u_s + buf * 4096 + (k2 * 8 + ul) * 64 + (ub4 << 2), src);
        }
        asm volatile("cp.async.commit_group;");
    };
    auto load_w = [&](int ch, float4& r0, float4& r1) {
        const float* src = weight + ((size_t)(wo * KKn + ch * 8 + wk2)) * Ln + l0;
        r0 = *(const float4*)(src);
        r1 = *(const float4*)(src + 4);
    };
    auto sts_w = [&](int buf, const float4& r0, const float4& r1) {
        float* wd = w_s + buf * 4096 + wk2 * 512 + wo;   // [k2][l][o], store l=0..7
        wd[0 * 64] = r0.x; wd[1 * 64] = r0.y; wd[2 * 64] = r0.z; wd[3 * 64] = r0.w;
        wd[4 * 64] = r1.x; wd[5 * 64] = r1.y; wd[6 * 64] = r1.z; wd[7 * 64] = r1.w;
    };

    // ---- pipeline prologue ----
    issue_u(0, 0);
    float4 wr0, wr1, wn0, wn1;
    load_w(0, wr0, wr1);

    const float* wbase0 = w_s + lv * 64 + ot * 8;
    const float* ubase0 = u_s + lv * 64 + bt * 8;

    for (int ch = 0; ch < 72; ch++) {
        int buf = ch & 1;
        sts_w(buf, wr0, wr1);
        if (ch + 1 < 72) {
            issue_u(ch + 1, buf ^ 1);
            load_w(ch + 1, wn0, wn1);
            asm volatile("cp.async.wait_group 1;");
        } else {
            asm volatile("cp.async.wait_group 0;");
        }
        __syncthreads();

        const float* wb = wbase0 + buf * 4096;
        const float* ub = ubase0 + buf * 4096;
#pragma unroll
        for (int kk = 0; kk < 8; kk++) {
            ulonglong2 wa = *(const ulonglong2*)(wb + kk * 512);
            ulonglong2 wc = *(const ulonglong2*)(wb + kk * 512 + 4);
            float4 ua = *(const float4*)(ub + kk * 512);
            float4 uc = *(const float4*)(ub + kk * 512 + 4);
            unsigned long long wv[4] = { wa.x, wa.y, wc.x, wc.y };
            unsigned long long u2[8] = { pk(ua.x), pk(ua.y), pk(ua.z), pk(ua.w),
                                         pk(uc.x), pk(uc.y), pk(uc.z), pk(uc.w) };
#pragma unroll
            for (int op = 0; op < 4; op++)
#pragma unroll
                for (int j = 0; j < 8; j++)
                    FFMA2(acc[op][j], wv[op], u2[j]);
        }
        __syncthreads();
        wr0 = wn0; wr1 = wn1;
    }

    // ---- epilogue: smem transpose for 32B-per-(b,o) coalesced output writes ----
    float* s_ep = smem;   // [64 b][68 pad] : s_ep[b*68 + o_t*8 + l]
    const int wb_ = tid & 63;       // writer b
    const int wot = tid >> 6;       // writer o_t

#pragma unroll
    for (int oi = 0; oi < 8; oi++) {
        int o_mine = ot * 8 + oi;
        float bv = bias[o_mine * Ln + l0 + lv];
#pragma unroll
        for (int j = 0; j < 8; j++) {
            float2 v2 = *reinterpret_cast<float2*>(&acc[oi >> 1][j]);
            float v = (oi & 1) ? v2.y : v2.x;
            s_ep[(bt * 8 + j) * 68 + ot * 8 + lv] = v + bv;
        }
        __syncthreads();
        // each thread writes one (b, o) pair's 8 pixels (32B contiguous)
        const float* sp = s_ep + wb_ * 68 + wot * 8;
        float4 v0 = *(const float4*)(sp);
        float4 v1 = *(const float4*)(sp + 4);
        int o_w = wot * 8 + oi;
        float* dst = out + ((size_t)(wb_ * On + o_w)) * Ln + l0;
        *(float4*)(dst)     = v0;
        *(float4*)(dst + 4) = v1;
        __syncthreads();
    }
}

// ---------------------------------------------------------------------------
extern "C" void kernel_launch(void* const* d_in, const int* in_sizes, int n_in,
                              void* d_out, int out_size) {
    const float* x      = (const float*)d_in[0];
    const float* weight = (const float*)d_in[1];
    const float* bias   = (const float*)d_in[2];
    float* out = (float*)d_out;

    cudaFuncSetAttribute(lc_kernel, cudaFuncAttributeMaxDynamicSharedMemorySize, 65536);

    border_kernel<<<2112, 256>>>();
    transpose_kernel<<<Cn * Hn, 256>>>(x);
    lc_kernel<<<Ln / 8, 512, 65536>>>(weight, bias, out);
}

// round 3
// speedup vs baseline: 1.0645x; 1.0069x over previous
#include <cuda_runtime.h>
#include <cstdint>

#define Bn 64
#define Cn 64
#define On 64
#define Hn 32
#define Wn 32
#define Ln 1024
#define KKn 576
#define HP 34
#define WP 34

// padded, transposed x: [c][hp][wp][b], b innermost for coalesced unfold gathers
__device__ float g_xTp[Cn * HP * WP * Bn];

// ---------------------------------------------------------------------------
// Kernel 1: zero the padded border of g_xTp
// ---------------------------------------------------------------------------
__global__ void border_kernel() {
    int idx = blockIdx.x * 256 + threadIdx.x;       // 64 c * 132 border cells * 64 b
    if (idx >= Cn * 132 * Bn) return;
    int b = idx & 63;
    int r = idx >> 6;
    int c = r / 132;
    int cell = r % 132;
    int hp, wp;
    if (cell < 34)       { hp = 0;  wp = cell; }
    else if (cell < 68)  { hp = 33; wp = cell - 34; }
    else if (cell < 100) { hp = cell - 68 + 1;  wp = 0; }
    else                 { hp = cell - 100 + 1; wp = 33; }
    g_xTp[((c * HP + hp) * WP + wp) * Bn + b] = 0.0f;
}

// ---------------------------------------------------------------------------
// Kernel 2: transpose x (B,C,H,W) -> xTp[c][h+1][w+1][b] via smem tile
// ---------------------------------------------------------------------------
__global__ void transpose_kernel(const float* __restrict__ x) {
    __shared__ float t[32][65];
    int c = blockIdx.x & 63;
    int h = blockIdx.x >> 6;
    int tid = threadIdx.x;

    int w  = tid & 31;
    int b0 = tid >> 5;                     // 0..7
#pragma unroll
    for (int p = 0; p < 8; p++) {
        int b = b0 * 8 + p;
        t[w][b] = x[((b * Cn + c) * Hn + h) * Wn + w];  // 128B coalesced reads
    }
    __syncthreads();
    int b  = tid & 63;
    int wq = tid >> 6;                     // 0..3
#pragma unroll
    for (int p = 0; p < 8; p++) {
        int ww = wq * 8 + p;
        g_xTp[((c * HP + (h + 1)) * WP + (ww + 1)) * Bn + b] = t[ww][b];  // 256B coalesced writes
    }
}

// ---------------------------------------------------------------------------
// Kernel 3: main locally-connected GEMM
//   grid = 128 CTAs (8 pixels each), 512 threads
//   thread tid -> (b_t = tid&7, o_t = (tid>>3)&7, l = tid>>6)
//   per-thread 8o x 8b outer product at one pixel, fp32x2-packed over o
// ---------------------------------------------------------------------------
__device__ __forceinline__ void cpa16(float* dst, const float* src) {
    unsigned d = (unsigned)__cvta_generic_to_shared(dst);
    asm volatile("cp.async.cg.shared.global [%0], [%1], 16;" :: "r"(d), "l"(src));
}
__device__ __forceinline__ unsigned long long pk(float v) {
    unsigned long long r;
    asm("mov.b64 %0, {%1, %1};" : "=l"(r) : "f"(v));
    return r;
}
#define FFMA2(a, wv, uv) asm("fma.rn.f32x2 %0, %1, %2, %0;" : "+l"(a) : "l"(wv), "l"(uv))

__global__ __launch_bounds__(512, 1)
void lc_kernel(const float* __restrict__ weight, const float* __restrict__ bias,
               float* __restrict__ out) {
    extern __shared__ float smem[];
    float* w_s = smem;            // [2][8k][8l][64o]  (16KB per buf)
    float* u_s = smem + 8192;     // [2][8k][8l][64b]

    const int tid = threadIdx.x;
    const int bt  = tid & 7;
    const int ot  = (tid >> 3) & 7;
    const int lv  = tid >> 6;
    const int l0  = blockIdx.x << 3;
    const int h   = l0 >> 5;         // row (constant for the whole CTA)
    const int w0  = l0 & 31;

    // u cp.async mapping: thread covers 2 float4s (k2 and k2+4), fixed (l,b4)
    const int ub4  = tid & 15;
    const int ul   = (tid >> 4) & 7;
    const int uk2a = tid >> 7;       // 0..3

    // w LDG/STS mapping: thread covers (o, k2), 8 l-values (32B contiguous in gmem)
    const int wo  = tid & 63;
    const int wk2 = tid >> 6;        // 0..7

    unsigned long long acc[4][8];
#pragma unroll
    for (int i = 0; i < 4; i++)
#pragma unroll
        for (int j = 0; j < 8; j++) acc[i][j] = 0ULL;

    // ---- helpers as lambdas ----
    auto issue_u = [&](int ch, int buf) {
#pragma unroll
        for (int t = 0; t < 2; t++) {
            int k2 = uk2a + 4 * t;
            int k  = ch * 8 + k2;
            int c   = (k * 7282) >> 16;        // k/9, exact for k<576
            int rem = k - 9 * c;
            int i   = (rem * 11) >> 5;         // rem/3
            int j   = rem - 3 * i;
            const float* src = g_xTp + (((c * HP) + h + i) * WP + (w0 + ul + j)) * Bn + (ub4 << 2);
            cpa16(u_s + buf * 4096 + (k2 * 8 + ul) * 64 + (ub4 << 2), src);
        }
        asm volatile("cp.async.commit_group;");
    };
    auto load_w = [&](int ch, float4& r0, float4& r1) {
        const float* src = weight + ((size_t)(wo * KKn + ch * 8 + wk2)) * Ln + l0;
        r0 = *(const float4*)(src);
        r1 = *(const float4*)(src + 4);
    };
    auto sts_w = [&](int buf, const float4& r0, const float4& r1) {
        float* wd = w_s + buf * 4096 + wk2 * 512 + wo;   // [k2][l][o], store l=0..7
        wd[0 * 64] = r0.x; wd[1 * 64] = r0.y; wd[2 * 64] = r0.z; wd[3 * 64] = r0.w;
        wd[4 * 64] = r1.x; wd[5 * 64] = r1.y; wd[6 * 64] = r1.z; wd[7 * 64] = r1.w;
    };

    // ---- pipeline prologue ----
    issue_u(0, 0);
    float4 wr0, wr1, wn0, wn1;
    load_w(0, wr0, wr1);

    const float* wbase0 = w_s + lv * 64 + ot * 8;
    const float* ubase0 = u_s + lv * 64 + bt * 8;

    for (int ch = 0; ch < 72; ch++) {
        int buf = ch & 1;
        sts_w(buf, wr0, wr1);
        if (ch + 1 < 72) {
            issue_u(ch + 1, buf ^ 1);
            load_w(ch + 1, wn0, wn1);
            asm volatile("cp.async.wait_group 1;");
        } else {
            asm volatile("cp.async.wait_group 0;");
        }
        __syncthreads();

        const float* wb = wbase0 + buf * 4096;
        const float* ub = ubase0 + buf * 4096;
#pragma unroll
        for (int kk = 0; kk < 8; kk++) {
            ulonglong2 wa = *(const ulonglong2*)(wb + kk * 512);
            ulonglong2 wc = *(const ulonglong2*)(wb + kk * 512 + 4);
            float4 ua = *(const float4*)(ub + kk * 512);
            float4 uc = *(const float4*)(ub + kk * 512 + 4);
            unsigned long long wv[4] = { wa.x, wa.y, wc.x, wc.y };
            unsigned long long u2[8] = { pk(ua.x), pk(ua.y), pk(ua.z), pk(ua.w),
                                         pk(uc.x), pk(uc.y), pk(uc.z), pk(uc.w) };
#pragma unroll
            for (int op = 0; op < 4; op++)
#pragma unroll
                for (int j = 0; j < 8; j++)
                    FFMA2(acc[op][j], wv[op], u2[j]);
        }
        __syncthreads();
        wr0 = wn0; wr1 = wn1;
    }

    // ---- epilogue: smem transpose for 32B-per-(b,o) coalesced output writes ----
    float* s_ep = smem;   // [64 b][68 pad] : s_ep[b*68 + o_t*8 + l]
    const int wb_ = tid & 63;       // writer b
    const int wot = tid >> 6;       // writer o_t

#pragma unroll
    for (int oi = 0; oi < 8; oi++) {
        int o_mine = ot * 8 + oi;
        float bv = bias[o_mine * Ln + l0 + lv];
#pragma unroll
        for (int j = 0; j < 8; j++) {
            float2 v2 = *reinterpret_cast<float2*>(&acc[oi >> 1][j]);
            float v = (oi & 1) ? v2.y : v2.x;
            s_ep[(bt * 8 + j) * 68 + ot * 8 + lv] = v + bv;
        }
        __syncthreads();
        // each thread writes one (b, o) pair's 8 pixels (32B contiguous)
        const float* sp = s_ep + wb_ * 68 + wot * 8;
        float4 v0 = *(const float4*)(sp);
        float4 v1 = *(const float4*)(sp + 4);
        int o_w = wot * 8 + oi;
        float* dst = out + ((size_t)(wb_ * On + o_w)) * Ln + l0;
        *(float4*)(dst)     = v0;
        *(float4*)(dst + 4) = v1;
        __syncthreads();
    }
}

// ---------------------------------------------------------------------------
extern "C" void kernel_launch(void* const* d_in, const int* in_sizes, int n_in,
                              void* d_out, int out_size) {
    const float* x      = (const float*)d_in[0];
    const float* weight = (const float*)d_in[1];
    const float* bias   = (const float*)d_in[2];
    float* out = (float*)d_out;

    cudaFuncSetAttribute(lc_kernel, cudaFuncAttributeMaxDynamicSharedMemorySize, 65536);

    border_kernel<<<2112, 256>>>();
    transpose_kernel<<<Cn * Hn, 256>>>(x);
    lc_kernel<<<Ln / 8, 512, 65536>>>(weight, bias, out);
}